// round 2
// baseline (speedup 1.0000x reference)
#include <cuda_runtime.h>
#include <cstdint>

typedef unsigned long long u64;

#define B_   4096
#define XD   128
#define YD   64
#define T_   200
#define LAT  100
#define G3   300
#define CH   50
#define R_   32
#define NB   (B_ / R_)     // 128 blocks
#define NT   256

// SMEM layout (float offsets). Dup buffers store every value twice ([k][2r],[2r+1]),
// stride 68, so LDS.128 yields two ready-packed f32x2 broadcast operands.
#define OFF_WHH 0          // [100][300]                     30000
#define OFF_BIH 30000      // [300]
#define OFF_BHH 30300      // [300]
#define OFF_BL1 30600      // [104]
#define OFF_BL2 30704      // [64]
#define OFF_H0  30768      // [100][68] dup                  6800
#define OFF_H1  37568      // [100][68] dup                  6800
#define OFF_AXD 44368      // [128][68] dup (aliased by O1D) 8704
#define OFF_YP  53072      // [64][33]                       2112
#define SMEM_FLOATS 55184  // 220736 bytes

__device__ __forceinline__ void fma2(u64 &d, u64 a, u64 b) {
    asm("fma.rn.f32x2 %0, %1, %2, %0;" : "+l"(d) : "l"(a), "l"(b));
}
__device__ __forceinline__ float2 unp(u64 v) {
    float2 f; asm("mov.b64 {%0, %1}, %2;" : "=f"(f.x), "=f"(f.y) : "l"(v));
    return f;
}
__device__ __forceinline__ float fsig(float x) {
    return __fdividef(1.0f, 1.0f + __expf(-x));
}
__device__ __forceinline__ float ftanh_(float x) {
    float e = __expf(2.0f * x);
    return 1.0f - __fdividef(2.0f, e + 1.0f);
}

// Packed 4rows x 4cols GEMM: A = dup SMEM buffer (stride 68), W gmem row-major.
__device__ __forceinline__ void gemm_p44(
    const float* __restrict__ sm, int aoff,
    const float* __restrict__ W, int ldw, int K,
    int j0, int r2, u64 acc[4][2])   // r2 = 2*r0
{
#pragma unroll
    for (int i = 0; i < 4; i++) { acc[i][0] = 0ull; acc[i][1] = 0ull; }
#pragma unroll 2
    for (int k = 0; k < K; k++) {
        const ulonglong2 a01 = *(const ulonglong2*)&sm[aoff + k * 68 + r2];
        const ulonglong2 a23 = *(const ulonglong2*)&sm[aoff + k * 68 + r2 + 4];
        const ulonglong2 w   = __ldg((const ulonglong2*)&W[k * ldw + j0]);
        fma2(acc[0][0], a01.x, w.x); fma2(acc[0][1], a01.x, w.y);
        fma2(acc[1][0], a01.y, w.x); fma2(acc[1][1], a01.y, w.y);
        fma2(acc[2][0], a23.x, w.x); fma2(acc[2][1], a23.x, w.y);
        fma2(acc[3][0], a23.y, w.x); fma2(acc[3][1], a23.y, w.y);
    }
}

extern "C" __global__ void __launch_bounds__(NT, 1) gru_kernel(
    const float* __restrict__ x, const float* __restrict__ y, const void* __restrict__ ymask,
    const float* __restrict__ Wmu1, const float* __restrict__ bmu1,
    const float* __restrict__ Wmu2, const float* __restrict__ bmu2,
    const float* __restrict__ Wih, const float* __restrict__ bih,
    const float* __restrict__ Whh, const float* __restrict__ bhh,
    const float* __restrict__ Wl1, const float* __restrict__ bl1,
    const float* __restrict__ Wl2, const float* __restrict__ bl2,
    const float* __restrict__ Wc1, const float* __restrict__ bc1,
    const float* __restrict__ Wc2, const float* __restrict__ bc2,
    float* __restrict__ out, int has_cls)
{
    extern __shared__ float sm[];
    const int tid  = threadIdx.x;
    const int lane = tid & 31;
    const int w    = tid >> 5;
    const int r0   = w << 2;          // 8 warps x 4 rows
    const int r2   = r0 << 1;         // dup index base
    const int b0   = blockIdx.x * R_;
    const int j0   = lane * 4;        // col quad base (lanes<25 cover j 0..99)

    // ---- stage Whh + biases; zero y_prev ----
    for (int i = tid; i < (LAT * G3) / 4; i += NT)
        ((float4*)(sm + OFF_WHH))[i] = __ldg(((const float4*)Whh) + i);
    for (int i = tid; i < G3; i += NT) { sm[OFF_BIH + i] = bih[i]; sm[OFF_BHH + i] = bhh[i]; }
    for (int i = tid; i < LAT; i += NT) sm[OFF_BL1 + i] = bl1[i];
    for (int i = tid; i < YD;  i += NT) sm[OFF_BL2 + i] = bl2[i];
    for (int i = tid; i < YD * 33; i += NT) sm[OFF_YP + i] = 0.f;

    // ---- mask dtype detection (uint8 / int32 / float32), deterministic ----
    const unsigned word = ((const unsigned*)ymask)[tid];
    const int big = __syncthreads_or((word & 0xFEFEFEFEu) != 0u);
    const int odd = __syncthreads_or((word & 0xFFFFFF00u) != 0u);
    const int mode = big ? 2 : (odd ? 0 : 1);

    // ---- stage x into AXD (dup) ----
    for (int e = tid; e < R_ * XD; e += NT) {
        const int r = e & 31, k = e >> 5;
        const float v = __ldg(&x[(size_t)(b0 + r) * XD + k]);
        *(float2*)&sm[OFF_AXD + k * 68 + 2 * r] = make_float2(v, v);
    }
    __syncthreads();

    // ---- hoist per-lane biases into registers ----
    float br[4], bz[4], bnx[4], bnh[4], bl1h[4], bl2h[4];
#pragma unroll
    for (int c = 0; c < 4; c++) {
        const int j = j0 + c;
        if (lane < 25) {
            br[c]  = sm[OFF_BIH + j] + sm[OFF_BHH + j];
            bz[c]  = sm[OFF_BIH + 100 + j] + sm[OFF_BHH + 100 + j];
            bnx[c] = sm[OFF_BIH + 200 + j];
            bnh[c] = sm[OFF_BHH + 200 + j];
            bl1h[c] = sm[OFF_BL1 + j];
        } else { br[c] = bz[c] = bnx[c] = bnh[c] = bl1h[c] = 0.f; }
        bl2h[c] = (lane < 16) ? sm[OFF_BL2 + j] : 0.f;
    }

    // ---- h0 = tanh(x @ Wmu1 + bmu1) @ Wmu2 + bmu2  (into H0) ----
    if (lane < 25) {
        u64 acc[4][2];
        gemm_p44(sm, OFF_AXD, Wmu1, LAT, XD, j0, r2, acc);
        const float4 bb = __ldg((const float4*)&bmu1[j0]);
        const float bc[4] = {bb.x, bb.y, bb.z, bb.w};
#pragma unroll
        for (int i = 0; i < 4; i++)
#pragma unroll
            for (int p = 0; p < 2; p++) {
                const float2 v = unp(acc[i][p]);
                const float o0 = ftanh_(v.x + bc[2 * p]);
                const float o1 = ftanh_(v.y + bc[2 * p + 1]);
                *(float2*)&sm[OFF_H1 + (j0 + 2 * p) * 68 + r2 + 2 * i]     = make_float2(o0, o0);
                *(float2*)&sm[OFF_H1 + (j0 + 2 * p + 1) * 68 + r2 + 2 * i] = make_float2(o1, o1);
            }
    }
    __syncthreads();
    if (lane < 25) {
        u64 acc[4][2];
        gemm_p44(sm, OFF_H1, Wmu2, LAT, LAT, j0, r2, acc);
        const float4 bb = __ldg((const float4*)&bmu2[j0]);
        const float bc[4] = {bb.x, bb.y, bb.z, bb.w};
#pragma unroll
        for (int i = 0; i < 4; i++)
#pragma unroll
            for (int p = 0; p < 2; p++) {
                const float2 v = unp(acc[i][p]);
                const float o0 = v.x + bc[2 * p];
                const float o1 = v.y + bc[2 * p + 1];
                *(float2*)&sm[OFF_H0 + (j0 + 2 * p) * 68 + r2 + 2 * i]     = make_float2(o0, o0);
                *(float2*)&sm[OFF_H0 + (j0 + 2 * p + 1) * 68 + r2 + 2 * i] = make_float2(o1, o1);
            }
    }

    // ---- prefetch y/mask for t=0 ----
    float yv[8], mfv[8];
    auto preload = [&](int t) {
#pragma unroll
        for (int i = 0; i < 8; i++) {
            const int e = tid + NT * i;
            const int r = e & 31, d = e >> 5;
            const size_t off = (size_t)(b0 + r) * (YD * T_) + (size_t)d * T_ + t;
            yv[i] = __ldg(&y[off]);
            float m;
            if (mode == 0)      m = (((const unsigned char*)ymask)[off] != 0) ? 1.f : 0.f;
            else if (mode == 1) m = (((const int*)ymask)[off] != 0) ? 1.f : 0.f;
            else                m = (((const float*)ymask)[off] != 0.f) ? 1.f : 0.f;
            mfv[i] = m;
        }
    };
    preload(0);
    __syncthreads();

    // ================= main recurrence =================
    for (int t = 0; t < T_; ++t) {
        const int rdH = (t & 1) ? OFF_H1 : OFF_H0;
        const int wrH = (t & 1) ? OFF_H0 : OFF_H1;

        // -- teacher forcing -> AXD (dup, k interleaved value/mask) --
#pragma unroll
        for (int i = 0; i < 8; i++) {
            const int e = tid + NT * i;
            const int r = e & 31, d = e >> 5;
            const float m  = mfv[i];
            const float yp = sm[OFF_YP + d * 33 + r];
            const float yin = (m != 0.f) ? yv[i] : yp;
            *(float2*)&sm[OFF_AXD + (2 * d) * 68 + 2 * r]     = make_float2(yin, yin);
            *(float2*)&sm[OFF_AXD + (2 * d + 1) * 68 + 2 * r] = make_float2(m, m);
        }
        if (t + 1 < T_) preload(t + 1);
        __syncthreads();

        if (lane < 25) {
            // -- fused GEMM1 (ax@Wih) + GEMM2 (h@Whh) in registers --
            u64 acc[3][4][2];   // [gate chunk r/z/nx][row][colpair]
            u64 accn[4][2];     // gh_n
#pragma unroll
            for (int i = 0; i < 4; i++) {
#pragma unroll
                for (int cc = 0; cc < 3; cc++) { acc[cc][i][0] = 0ull; acc[cc][i][1] = 0ull; }
                accn[i][0] = 0ull; accn[i][1] = 0ull;
            }
#pragma unroll 2
            for (int k = 0; k < XD; k++) {
                const ulonglong2 a01 = *(const ulonglong2*)&sm[OFF_AXD + k * 68 + r2];
                const ulonglong2 a23 = *(const ulonglong2*)&sm[OFF_AXD + k * 68 + r2 + 4];
#pragma unroll
                for (int cc = 0; cc < 3; cc++) {
                    const ulonglong2 wv = __ldg((const ulonglong2*)&Wih[k * G3 + j0 + cc * 100]);
                    fma2(acc[cc][0][0], a01.x, wv.x); fma2(acc[cc][0][1], a01.x, wv.y);
                    fma2(acc[cc][1][0], a01.y, wv.x); fma2(acc[cc][1][1], a01.y, wv.y);
                    fma2(acc[cc][2][0], a23.x, wv.x); fma2(acc[cc][2][1], a23.x, wv.y);
                    fma2(acc[cc][3][0], a23.y, wv.x); fma2(acc[cc][3][1], a23.y, wv.y);
                }
            }
#pragma unroll 2
            for (int k = 0; k < LAT; k++) {
                const ulonglong2 a01 = *(const ulonglong2*)&sm[rdH + k * 68 + r2];
                const ulonglong2 a23 = *(const ulonglong2*)&sm[rdH + k * 68 + r2 + 4];
                {   // r chunk
                    const ulonglong2 wv = *(const ulonglong2*)&sm[OFF_WHH + k * G3 + j0];
                    fma2(acc[0][0][0], a01.x, wv.x); fma2(acc[0][0][1], a01.x, wv.y);
                    fma2(acc[0][1][0], a01.y, wv.x); fma2(acc[0][1][1], a01.y, wv.y);
                    fma2(acc[0][2][0], a23.x, wv.x); fma2(acc[0][2][1], a23.x, wv.y);
                    fma2(acc[0][3][0], a23.y, wv.x); fma2(acc[0][3][1], a23.y, wv.y);
                }
                {   // z chunk
                    const ulonglong2 wv = *(const ulonglong2*)&sm[OFF_WHH + k * G3 + 100 + j0];
                    fma2(acc[1][0][0], a01.x, wv.x); fma2(acc[1][0][1], a01.x, wv.y);
                    fma2(acc[1][1][0], a01.y, wv.x); fma2(acc[1][1][1], a01.y, wv.y);
                    fma2(acc[1][2][0], a23.x, wv.x); fma2(acc[1][2][1], a23.x, wv.y);
                    fma2(acc[1][3][0], a23.y, wv.x); fma2(acc[1][3][1], a23.y, wv.y);
                }
                {   // n chunk (hidden part separate)
                    const ulonglong2 wv = *(const ulonglong2*)&sm[OFF_WHH + k * G3 + 200 + j0];
                    fma2(accn[0][0], a01.x, wv.x); fma2(accn[0][1], a01.x, wv.y);
                    fma2(accn[1][0], a01.y, wv.x); fma2(accn[1][1], a01.y, wv.y);
                    fma2(accn[2][0], a23.x, wv.x); fma2(accn[2][1], a23.x, wv.y);
                    fma2(accn[3][0], a23.y, wv.x); fma2(accn[3][1], a23.y, wv.y);
                }
            }
            // -- gates in registers, write h_new (dup) --
#pragma unroll
            for (int i = 0; i < 4; i++) {
                const int rr2 = r2 + 2 * i;
#pragma unroll
                for (int p = 0; p < 2; p++) {
                    const float2 gr = unp(acc[0][i][p]);
                    const float2 gz = unp(acc[1][i][p]);
                    const float2 gx = unp(acc[2][i][p]);
                    const float2 gh = unp(accn[i][p]);
                    const int c0 = 2 * p, c1 = 2 * p + 1;
                    const int ja = j0 + c0, jb = j0 + c1;
                    {
                        const float rg = fsig(gr.x + br[c0]);
                        const float z  = fsig(gz.x + bz[c0]);
                        const float n  = ftanh_(gx.x + bnx[c0] + rg * (gh.x + bnh[c0]));
                        const float ho = sm[rdH + ja * 68 + rr2];
                        const float hn = (1.f - z) * n + z * ho;
                        *(float2*)&sm[wrH + ja * 68 + rr2] = make_float2(hn, hn);
                    }
                    {
                        const float rg = fsig(gr.y + br[c1]);
                        const float z  = fsig(gz.y + bz[c1]);
                        const float n  = ftanh_(gx.y + bnx[c1] + rg * (gh.y + bnh[c1]));
                        const float ho = sm[rdH + jb * 68 + rr2];
                        const float hn = (1.f - z) * n + z * ho;
                        *(float2*)&sm[wrH + jb * 68 + rr2] = make_float2(hn, hn);
                    }
                }
            }
        }
        __syncthreads();

        // -- GEMM3: o1 = tanh(h_new @ Wl1 + bl1) -> O1D (aliases AXD) --
        if (lane < 25) {
            u64 a3[4][2];
            gemm_p44(sm, wrH, Wl1, LAT, LAT, j0, r2, a3);
#pragma unroll
            for (int i = 0; i < 4; i++)
#pragma unroll
                for (int p = 0; p < 2; p++) {
                    const float2 v = unp(a3[i][p]);
                    const float o0 = ftanh_(v.x + bl1h[2 * p]);
                    const float o1 = ftanh_(v.y + bl1h[2 * p + 1]);
                    *(float2*)&sm[OFF_AXD + (j0 + 2 * p) * 68 + r2 + 2 * i]     = make_float2(o0, o0);
                    *(float2*)&sm[OFF_AXD + (j0 + 2 * p + 1) * 68 + r2 + 2 * i] = make_float2(o1, o1);
                }
        }
        __syncthreads();

        // -- GEMM4: out_t = o1 @ Wl2 + bl2 -> gmem + y_prev --
        if (lane < 16) {
            u64 a4[4][2];
            gemm_p44(sm, OFF_AXD, Wl2, YD, LAT, j0, r2, a4);
#pragma unroll
            for (int i = 0; i < 4; i++) {
                const int rr = r0 + i;
#pragma unroll
                for (int p = 0; p < 2; p++) {
                    const float2 v = unp(a4[i][p]);
                    const float v0 = v.x + bl2h[2 * p];
                    const float v1 = v.y + bl2h[2 * p + 1];
                    const int ja = j0 + 2 * p, jb = ja + 1;
                    out[(size_t)(b0 + rr) * (YD * T_) + (size_t)ja * T_ + t] = v0;
                    out[(size_t)(b0 + rr) * (YD * T_) + (size_t)jb * T_ + t] = v1;
                    sm[OFF_YP + ja * 33 + rr] = v0;
                    sm[OFF_YP + jb * 33 + rr] = v1;
                }
            }
        }
        __syncthreads();
    }

    // ---- classifier: sigmoid(relu(h_T @ Wc1 + bc1) @ Wc2 + bc2); h_T in H0 (T even) ----
    if (has_cls) {
        for (int idx = tid; idx < R_ * CH; idx += NT) {
            const int r = idx & 31, c = idx >> 5;
            float acc = __ldg(&bc1[c]);
            for (int k = 0; k < LAT; k++)
                acc = fmaf(sm[OFF_H0 + k * 68 + 2 * r], __ldg(&Wc1[k * CH + c]), acc);
            sm[OFF_AXD + c * 68 + r] = fmaxf(acc, 0.f);
        }
        __syncthreads();
        if (tid < R_) {
            float acc = __ldg(&bc2[0]);
            for (int c = 0; c < CH; c++)
                acc = fmaf(sm[OFF_AXD + c * 68 + tid], __ldg(&Wc2[c]), acc);
            out[(size_t)B_ * YD * T_ + b0 + tid] = fsig(acc);
        }
    }
}

extern "C" void kernel_launch(void* const* d_in, const int* in_sizes, int n_in,
                              void* d_out, int out_size)
{
    cudaFuncSetAttribute(gru_kernel, cudaFuncAttributeMaxDynamicSharedMemorySize,
                         SMEM_FLOATS * (int)sizeof(float));
    const int has_cls = (out_size > B_ * YD * T_) ? 1 : 0;
    gru_kernel<<<NB, NT, SMEM_FLOATS * sizeof(float)>>>(
        (const float*)d_in[0],   // x
        (const float*)d_in[1],   // y
        d_in[2],                 // y_mask (dtype auto-detected)
        (const float*)d_in[3],  (const float*)d_in[4],   // Wmu1, bmu1
        (const float*)d_in[5],  (const float*)d_in[6],   // Wmu2, bmu2
        (const float*)d_in[11], (const float*)d_in[12],  // Wih, bih
        (const float*)d_in[13], (const float*)d_in[14],  // Whh, bhh
        (const float*)d_in[15], (const float*)d_in[16],  // Wl1, bl1
        (const float*)d_in[17], (const float*)d_in[18],  // Wl2, bl2
        (const float*)d_in[19], (const float*)d_in[20],  // Wc1, bc1
        (const float*)d_in[21], (const float*)d_in[22],  // Wc2, bc2
        (float*)d_out, has_cls);
}

// round 3
// speedup vs baseline: 1.2717x; 1.2717x over previous
#include <cuda_runtime.h>
#include <cstdint>

#define B_   4096
#define XD   128
#define YD   64
#define T_   200
#define LAT  100
#define G3   300
#define CH   50
#define R_   32
#define NB   (B_ / R_)     // 128 blocks
#define NT   1024          // 32 warps -> 8 per SMSP

// SMEM layout (float offsets)
#define OFF_WHH 0          // [100][300]   30000
#define OFF_BIH 30000      // [300]
#define OFF_BHH 30300      // [300]
#define OFF_BL1 30600      // [104]
#define OFF_BL2 30704      // [64]
#define OFF_H   30768      // [100][36]  ([k][r])  3600
#define OFF_AX  34368      // [128][32]  ([k][r])  4096
#define OFF_YP  38464      // [64][33]   ([d][r])  2112
#define OFF_GX  40576      // [32][304]  ([r][j])  9728
#define OFF_GHN 50304      // [32][104]  ([r][j])  3328
#define OFF_O1  OFF_GX     // [100][36] overlays GX (safe: barrier-separated)
#define SMEM_FLOATS 53632  // 214528 bytes

__device__ __forceinline__ float fsig(float x) {
    return __fdividef(1.0f, 1.0f + __expf(-x));
}
__device__ __forceinline__ float ftanh_(float x) {
    float e = __expf(2.0f * x);
    return 1.0f - __fdividef(2.0f, e + 1.0f);
}

extern "C" __global__ void __launch_bounds__(NT, 1) gru_kernel(
    const float* __restrict__ x, const float* __restrict__ y, const void* __restrict__ ymask,
    const float* __restrict__ Wmu1, const float* __restrict__ bmu1,
    const float* __restrict__ Wmu2, const float* __restrict__ bmu2,
    const float* __restrict__ Wih, const float* __restrict__ bih,
    const float* __restrict__ Whh, const float* __restrict__ bhh,
    const float* __restrict__ Wl1, const float* __restrict__ bl1,
    const float* __restrict__ Wl2, const float* __restrict__ bl2,
    const float* __restrict__ Wc1, const float* __restrict__ bc1,
    const float* __restrict__ Wc2, const float* __restrict__ bc2,
    float* __restrict__ out, int has_cls)
{
    extern __shared__ float sm[];
    const int tid  = threadIdx.x;
    const int lane = tid & 31;
    const int wid  = tid >> 5;        // 0..31
    const int role = wid >> 3;        // 0:r  1:z  2:nx  3:nh  (2 warps/role/SMSP)
    const int q    = wid & 7;         // row quad 0..7
    const int r0   = q << 2;
    const int b0   = blockIdx.x * R_;
    const int j0   = lane * 4;        // lanes<25 cover j=0..99 within a 100-col chunk

    // ---- stage Whh + biases; zero y_prev ----
    for (int i = tid; i < (LAT * G3) / 4; i += NT)
        ((float4*)(sm + OFF_WHH))[i] = __ldg(((const float4*)Whh) + i);
    for (int i = tid; i < G3; i += NT) { sm[OFF_BIH + i] = bih[i]; sm[OFF_BHH + i] = bhh[i]; }
    for (int i = tid; i < LAT; i += NT) sm[OFF_BL1 + i] = bl1[i];
    for (int i = tid; i < YD;  i += NT) sm[OFF_BL2 + i] = bl2[i];
    for (int i = tid; i < YD * 33; i += NT) sm[OFF_YP + i] = 0.f;

    // ---- mask dtype detection (uint8 / int32 / float32), deterministic ----
    const unsigned word = ((const unsigned*)ymask)[tid];
    const int big = __syncthreads_or((word & 0xFEFEFEFEu) != 0u);
    const int odd = __syncthreads_or((word & 0xFFFFFF00u) != 0u);
    const int mode = big ? 2 : (odd ? 0 : 1);

    // ---- stage x into AX ([k][r]) ----
#pragma unroll
    for (int i = 0; i < 4; i++) {
        const int e = tid + NT * i;       // 4096 = 32r x 128k
        const int r = e & 31, k = e >> 5;
        sm[OFF_AX + k * 32 + r] = __ldg(&x[(size_t)(b0 + r) * XD + k]);
    }
    __syncthreads();

    // ---- h0: tmp = tanh(x @ Wmu1 + bmu1); h0 = tmp @ Wmu2 + bmu2 ----
    // warp = row (32 warps, 32 rows); lanes<25 cover 100 cols
    if (lane < 25) {
        float acc[4] = {0.f, 0.f, 0.f, 0.f};
#pragma unroll 4
        for (int k = 0; k < XD; k++) {
            const float a = sm[OFF_AX + k * 32 + wid];
            const float4 wv = __ldg((const float4*)&Wmu1[k * LAT + j0]);
            acc[0] = fmaf(a, wv.x, acc[0]); acc[1] = fmaf(a, wv.y, acc[1]);
            acc[2] = fmaf(a, wv.z, acc[2]); acc[3] = fmaf(a, wv.w, acc[3]);
        }
        const float4 bb = __ldg((const float4*)&bmu1[j0]);
        sm[OFF_O1 + (j0 + 0) * 36 + wid] = ftanh_(acc[0] + bb.x);
        sm[OFF_O1 + (j0 + 1) * 36 + wid] = ftanh_(acc[1] + bb.y);
        sm[OFF_O1 + (j0 + 2) * 36 + wid] = ftanh_(acc[2] + bb.z);
        sm[OFF_O1 + (j0 + 3) * 36 + wid] = ftanh_(acc[3] + bb.w);
    }
    __syncthreads();
    if (lane < 25) {
        float acc[4] = {0.f, 0.f, 0.f, 0.f};
#pragma unroll 4
        for (int k = 0; k < LAT; k++) {
            const float a = sm[OFF_O1 + k * 36 + wid];
            const float4 wv = __ldg((const float4*)&Wmu2[k * LAT + j0]);
            acc[0] = fmaf(a, wv.x, acc[0]); acc[1] = fmaf(a, wv.y, acc[1]);
            acc[2] = fmaf(a, wv.z, acc[2]); acc[3] = fmaf(a, wv.w, acc[3]);
        }
        const float4 bb = __ldg((const float4*)&bmu2[j0]);
        sm[OFF_H + (j0 + 0) * 36 + wid] = acc[0] + bb.x;
        sm[OFF_H + (j0 + 1) * 36 + wid] = acc[1] + bb.y;
        sm[OFF_H + (j0 + 2) * 36 + wid] = acc[2] + bb.z;
        sm[OFF_H + (j0 + 3) * 36 + wid] = acc[3] + bb.w;
    }

    // ---- prefetch y/mask for t=0 (2048 = 32r x 64d elems, 2 per thread) ----
    float yv[2], mfv[2];
    auto preload = [&](int t) {
#pragma unroll
        for (int i = 0; i < 2; i++) {
            const int e = tid + NT * i;
            const int r = e & 31, d = e >> 5;
            const size_t off = (size_t)(b0 + r) * (YD * T_) + (size_t)d * T_ + t;
            yv[i] = __ldg(&y[off]);
            float m;
            if (mode == 0)      m = (((const unsigned char*)ymask)[off] != 0) ? 1.f : 0.f;
            else if (mode == 1) m = (((const int*)ymask)[off] != 0) ? 1.f : 0.f;
            else                m = (((const float*)ymask)[off] != 0.f) ? 1.f : 0.f;
            mfv[i] = m;
        }
    };
    preload(0);
    __syncthreads();

    // ================= main recurrence =================
    for (int t = 0; t < T_; ++t) {
        // -- teacher forcing -> AX ([k][r], k interleaved value/mask) --
#pragma unroll
        for (int i = 0; i < 2; i++) {
            const int e = tid + NT * i;
            const int r = e & 31, d = e >> 5;
            const float m  = mfv[i];
            const float yp = sm[OFF_YP + d * 33 + r];
            const float yin = (m != 0.f) ? yv[i] : yp;
            sm[OFF_AX + (2 * d) * 32 + r]     = yin;
            sm[OFF_AX + (2 * d + 1) * 32 + r] = m;
        }
        if (t + 1 < T_) preload(t + 1);
        __syncthreads();

        // -- fused GEMM1 (ax@Wih) + GEMM2 (h@Whh) by role --
        if (lane < 25) {
            float acc[4] = {0.f, 0.f, 0.f, 0.f};
            float a4x, a4y, a4z, a4w;
            if (role == 0 || role == 1 || role == 2) {
                // x-side: k over 128, Wih column chunk role*100
                const float* Wp = Wih + role * 100 + j0;
#pragma unroll 4
                for (int k = 0; k < XD; k++) {
                    const float4 a = *(const float4*)&sm[OFF_AX + k * 32 + r0];
                    const float4 wv = __ldg((const float4*)&Wp[k * G3]);
                    acc[0] = fmaf(a.x, wv.x, acc[0]); acc[1] = fmaf(a.x, wv.y, acc[1]);
                    acc[2] = fmaf(a.x, wv.z, acc[2]); acc[3] = fmaf(a.x, wv.w, acc[3]);
                    a4x = acc[0]; a4y = acc[1]; a4z = acc[2]; a4w = acc[3];
                    // rows 1..3
                    acc[0] = a4x; acc[1] = a4y; acc[2] = a4z; acc[3] = a4w; // (no-op keepalive)
                    // handled below via full quad unroll
                }
            }
            (void)a4x; (void)a4y; (void)a4z; (void)a4w;
            acc[0] = acc[0]; // placeholder; real implementation below
        }
        // NOTE: the block above is replaced by the explicit quad version:
        if (lane < 25) {
            float acc[4][4];
#pragma unroll
            for (int i = 0; i < 4; i++)
#pragma unroll
                for (int c = 0; c < 4; c++) acc[i][c] = 0.f;

            if (role < 3) {
                // x-side accumulation (roles r, z, nx): k over 128
                const float* Wp = Wih + role * 100 + j0;
#pragma unroll 4
                for (int k = 0; k < XD; k++) {
                    const float4 a = *(const float4*)&sm[OFF_AX + k * 32 + r0];
                    const float4 wv = __ldg((const float4*)&Wp[k * G3]);
                    acc[0][0] = fmaf(a.x, wv.x, acc[0][0]); acc[0][1] = fmaf(a.x, wv.y, acc[0][1]);
                    acc[0][2] = fmaf(a.x, wv.z, acc[0][2]); acc[0][3] = fmaf(a.x, wv.w, acc[0][3]);
                    acc[1][0] = fmaf(a.y, wv.x, acc[1][0]); acc[1][1] = fmaf(a.y, wv.y, acc[1][1]);
                    acc[1][2] = fmaf(a.y, wv.z, acc[1][2]); acc[1][3] = fmaf(a.y, wv.w, acc[1][3]);
                    acc[2][0] = fmaf(a.z, wv.x, acc[2][0]); acc[2][1] = fmaf(a.z, wv.y, acc[2][1]);
                    acc[2][2] = fmaf(a.z, wv.z, acc[2][2]); acc[2][3] = fmaf(a.z, wv.w, acc[2][3]);
                    acc[3][0] = fmaf(a.w, wv.x, acc[3][0]); acc[3][1] = fmaf(a.w, wv.y, acc[3][1]);
                    acc[3][2] = fmaf(a.w, wv.z, acc[3][2]); acc[3][3] = fmaf(a.w, wv.w, acc[3][3]);
                }
            }
            if (role == 0 || role == 1 || role == 3) {
                // h-side accumulation (roles r, z, nh): k over 100
                const int co = (role == 3) ? 200 : role * 100;
                const float* Wp = sm + OFF_WHH + co + j0;
#pragma unroll 4
                for (int k = 0; k < LAT; k++) {
                    const float4 a = *(const float4*)&sm[OFF_H + k * 36 + r0];
                    const float4 wv = *(const float4*)&Wp[k * G3];
                    acc[0][0] = fmaf(a.x, wv.x, acc[0][0]); acc[0][1] = fmaf(a.x, wv.y, acc[0][1]);
                    acc[0][2] = fmaf(a.x, wv.z, acc[0][2]); acc[0][3] = fmaf(a.x, wv.w, acc[0][3]);
                    acc[1][0] = fmaf(a.y, wv.x, acc[1][0]); acc[1][1] = fmaf(a.y, wv.y, acc[1][1]);
                    acc[1][2] = fmaf(a.y, wv.z, acc[1][2]); acc[1][3] = fmaf(a.y, wv.w, acc[1][3]);
                    acc[2][0] = fmaf(a.z, wv.x, acc[2][0]); acc[2][1] = fmaf(a.z, wv.y, acc[2][1]);
                    acc[2][2] = fmaf(a.z, wv.z, acc[2][2]); acc[2][3] = fmaf(a.z, wv.w, acc[2][3]);
                    acc[3][0] = fmaf(a.w, wv.x, acc[3][0]); acc[3][1] = fmaf(a.w, wv.y, acc[3][1]);
                    acc[3][2] = fmaf(a.w, wv.z, acc[3][2]); acc[3][3] = fmaf(a.w, wv.w, acc[3][3]);
                }
            }
            // store partials
            if (role < 3) {
                const int co = role * 100;   // roles r,z: x+h sum; role nx: x part
#pragma unroll
                for (int i = 0; i < 4; i++)
                    *(float4*)&sm[OFF_GX + (r0 + i) * 304 + co + j0] =
                        make_float4(acc[i][0], acc[i][1], acc[i][2], acc[i][3]);
            } else {
#pragma unroll
                for (int i = 0; i < 4; i++)
                    *(float4*)&sm[OFF_GHN + (r0 + i) * 104 + j0] =
                        make_float4(acc[i][0], acc[i][1], acc[i][2], acc[i][3]);
            }
        }
        __syncthreads();

        // -- gates: r,z = sigmoid; n = tanh(gxn + r*ghn); h = (1-z)*n + z*h --
#pragma unroll
        for (int it = 0; it < 4; ++it) {
            const int idx = tid + NT * it;
            if (idx < R_ * LAT) {
                const int r = idx / LAT;
                const int j = idx - r * LAT;
                const float g_r = sm[OFF_GX + r * 304 + j]       + sm[OFF_BIH + j]       + sm[OFF_BHH + j];
                const float g_z = sm[OFF_GX + r * 304 + 100 + j] + sm[OFF_BIH + 100 + j] + sm[OFF_BHH + 100 + j];
                const float gxn = sm[OFF_GX + r * 304 + 200 + j] + sm[OFF_BIH + 200 + j];
                const float ghn = sm[OFF_GHN + r * 104 + j]      + sm[OFF_BHH + 200 + j];
                const float rg = fsig(g_r);
                const float z  = fsig(g_z);
                const float n  = ftanh_(gxn + rg * ghn);
                const float hd = sm[OFF_H + j * 36 + r];
                sm[OFF_H + j * 36 + r] = (1.f - z) * n + z * hd;
            }
        }
        __syncthreads();

        // -- GEMM3: o1 = tanh(h @ Wl1 + bl1); warp = row --
        if (lane < 25) {
            float acc[4] = {0.f, 0.f, 0.f, 0.f};
#pragma unroll 4
            for (int k = 0; k < LAT; k++) {
                const float a = sm[OFF_H + k * 36 + wid];
                const float4 wv = __ldg((const float4*)&Wl1[k * LAT + j0]);
                acc[0] = fmaf(a, wv.x, acc[0]); acc[1] = fmaf(a, wv.y, acc[1]);
                acc[2] = fmaf(a, wv.z, acc[2]); acc[3] = fmaf(a, wv.w, acc[3]);
            }
            const float4 bb = *(const float4*)&sm[OFF_BL1 + j0];
            sm[OFF_O1 + (j0 + 0) * 36 + wid] = ftanh_(acc[0] + bb.x);
            sm[OFF_O1 + (j0 + 1) * 36 + wid] = ftanh_(acc[1] + bb.y);
            sm[OFF_O1 + (j0 + 2) * 36 + wid] = ftanh_(acc[2] + bb.z);
            sm[OFF_O1 + (j0 + 3) * 36 + wid] = ftanh_(acc[3] + bb.w);
        }
        __syncthreads();

        // -- GEMM4: out_t = o1 @ Wl2 + bl2; warp = row, lanes<16 cover 64 cols --
        if (lane < 16) {
            float acc[4] = {0.f, 0.f, 0.f, 0.f};
#pragma unroll 4
            for (int k = 0; k < LAT; k++) {
                const float a = sm[OFF_O1 + k * 36 + wid];
                const float4 wv = __ldg((const float4*)&Wl2[k * YD + j0]);
                acc[0] = fmaf(a, wv.x, acc[0]); acc[1] = fmaf(a, wv.y, acc[1]);
                acc[2] = fmaf(a, wv.z, acc[2]); acc[3] = fmaf(a, wv.w, acc[3]);
            }
            const float4 bb = *(const float4*)&sm[OFF_BL2 + j0];
            const float v[4] = {acc[0] + bb.x, acc[1] + bb.y, acc[2] + bb.z, acc[3] + bb.w};
            float* op = out + (size_t)(b0 + wid) * (YD * T_) + (size_t)j0 * T_ + t;
#pragma unroll
            for (int c = 0; c < 4; c++) {
                op[(size_t)c * T_] = v[c];
                sm[OFF_YP + (j0 + c) * 33 + wid] = v[c];
            }
        }
        __syncthreads();
    }

    // ---- classifier: sigmoid(relu(h_T @ Wc1 + bc1) @ Wc2 + bc2) ----
    if (has_cls) {
        for (int idx = tid; idx < R_ * CH; idx += NT) {
            const int r = idx & 31, c = idx >> 5;
            float acc = __ldg(&bc1[c]);
            for (int k = 0; k < LAT; k++)
                acc = fmaf(sm[OFF_H + k * 36 + r], __ldg(&Wc1[k * CH + c]), acc);
            sm[OFF_O1 + c * 36 + r] = fmaxf(acc, 0.f);
        }
        __syncthreads();
        if (tid < R_) {
            float acc = __ldg(&bc2[0]);
            for (int c = 0; c < CH; c++)
                acc = fmaf(sm[OFF_O1 + c * 36 + tid], __ldg(&Wc2[c]), acc);
            out[(size_t)B_ * YD * T_ + b0 + tid] = fsig(acc);
        }
    }
}

extern "C" void kernel_launch(void* const* d_in, const int* in_sizes, int n_in,
                              void* d_out, int out_size)
{
    cudaFuncSetAttribute(gru_kernel, cudaFuncAttributeMaxDynamicSharedMemorySize,
                         SMEM_FLOATS * (int)sizeof(float));
    const int has_cls = (out_size > B_ * YD * T_) ? 1 : 0;
    gru_kernel<<<NB, NT, SMEM_FLOATS * sizeof(float)>>>(
        (const float*)d_in[0],   // x
        (const float*)d_in[1],   // y
        d_in[2],                 // y_mask (dtype auto-detected)
        (const float*)d_in[3],  (const float*)d_in[4],   // Wmu1, bmu1
        (const float*)d_in[5],  (const float*)d_in[6],   // Wmu2, bmu2
        (const float*)d_in[11], (const float*)d_in[12],  // Wih, bih
        (const float*)d_in[13], (const float*)d_in[14],  // Whh, bhh
        (const float*)d_in[15], (const float*)d_in[16],  // Wl1, bl1
        (const float*)d_in[17], (const float*)d_in[18],  // Wl2, bl2
        (const float*)d_in[19], (const float*)d_in[20],  // Wc1, bc1
        (const float*)d_in[21], (const float*)d_in[22],  // Wc2, bc2
        (float*)d_out, has_cls);
}